// round 4
// baseline (speedup 1.0000x reference)
#include <cuda_runtime.h>
#include <cuda_bf16.h>
#include <cstdint>
#include <math.h>

// Problem constants
#define HWDIM 80
#define NPIX  6400
#define DIM   512
#define QKVN  1536
#define NHEAD 8
#define HD    64
#define KWIN  7

// Scratch (allocation-free rule: __device__ globals)
__device__ float g_qkv[(size_t)NPIX * QKVN];
__device__ __nv_bfloat16 g_xhi[(size_t)NPIX * DIM];
__device__ __nv_bfloat16 g_xlo[(size_t)NPIX * DIM];
__device__ __nv_bfloat16 g_w1hi[(size_t)QKVN * DIM];
__device__ __nv_bfloat16 g_w1lo[(size_t)QKVN * DIM];
__device__ __nv_bfloat16 g_ahi[(size_t)NPIX * DIM];
__device__ __nv_bfloat16 g_alo[(size_t)NPIX * DIM];
__device__ __nv_bfloat16 g_w2hi[(size_t)DIM * DIM];
__device__ __nv_bfloat16 g_w2lo[(size_t)DIM * DIM];

// ---------------------------------------------------------------------------
// fp32 -> bf16 hi/lo split (elementwise). n must be a multiple of 1024.
// ---------------------------------------------------------------------------
__global__ void __launch_bounds__(256) cvt_hilo(
    const float* __restrict__ src,
    __nv_bfloat16* __restrict__ hi, __nv_bfloat16* __restrict__ lo)
{
    const int i = (blockIdx.x * 256 + threadIdx.x) * 4;
    float4 v = *(const float4*)(src + i);
    float f[4] = {v.x, v.y, v.z, v.w};
    __nv_bfloat16 h[4], l[4];
#pragma unroll
    for (int k = 0; k < 4; k++) {
        h[k] = __float2bfloat16(f[k]);
        l[k] = __float2bfloat16(f[k] - __bfloat162float(h[k]));
    }
    uint2 ph, pl;
    {
        __nv_bfloat162 t;
        t = __nv_bfloat162(h[0], h[1]); ph.x = *(uint32_t*)&t;
        t = __nv_bfloat162(h[2], h[3]); ph.y = *(uint32_t*)&t;
        t = __nv_bfloat162(l[0], l[1]); pl.x = *(uint32_t*)&t;
        t = __nv_bfloat162(l[2], l[3]); pl.y = *(uint32_t*)&t;
    }
    *(uint2*)(hi + i) = ph;
    *(uint2*)(lo + i) = pl;
}

// ---------------------------------------------------------------------------
// mma.sync bf16 GEMM (3xBF16 compensated): C[M,N] = A[M,K] @ B[N,K]^T + bias
// ---------------------------------------------------------------------------
#define BK 32
#define ROWB 80
#define MATB (128 * ROWB)
#define STAGEB (4 * MATB)
#define GEMM_SMEM (2 * STAGEB)

__device__ __forceinline__ uint32_t smem_u32(const void* p) {
    uint32_t a;
    asm("{ .reg .u64 t; cvta.to.shared.u64 t, %1; cvt.u32.u64 %0, t; }"
        : "=r"(a) : "l"(p));
    return a;
}
__device__ __forceinline__ void cp16(uint32_t dst, const void* src) {
    asm volatile("cp.async.cg.shared.global [%0], [%1], 16;"
                 :: "r"(dst), "l"(src));
}
__device__ __forceinline__ void cp_commit() {
    asm volatile("cp.async.commit_group;" ::: "memory");
}
__device__ __forceinline__ void cp_wait1() {
    asm volatile("cp.async.wait_group 1;" ::: "memory");
}
__device__ __forceinline__ void ldmx4(uint32_t* r, uint32_t addr) {
    asm volatile("ldmatrix.sync.aligned.m8n8.x4.shared.b16 {%0,%1,%2,%3}, [%4];"
                 : "=r"(r[0]), "=r"(r[1]), "=r"(r[2]), "=r"(r[3]) : "r"(addr));
}
__device__ __forceinline__ void ldmx2(uint32_t* r, uint32_t addr) {
    asm volatile("ldmatrix.sync.aligned.m8n8.x2.shared.b16 {%0,%1}, [%2];"
                 : "=r"(r[0]), "=r"(r[1]) : "r"(addr));
}
__device__ __forceinline__ void mma_bf16(float* c, const uint32_t* a, const uint32_t* b) {
    asm volatile(
        "mma.sync.aligned.m16n8k16.row.col.f32.bf16.bf16.f32 "
        "{%0,%1,%2,%3}, {%4,%5,%6,%7}, {%8,%9}, {%0,%1,%2,%3};"
        : "+f"(c[0]), "+f"(c[1]), "+f"(c[2]), "+f"(c[3])
        : "r"(a[0]), "r"(a[1]), "r"(a[2]), "r"(a[3]), "r"(b[0]), "r"(b[1]));
}

__global__ void __launch_bounds__(256, 2) gemm_bf16x3(
    const __nv_bfloat16* __restrict__ Ahi, const __nv_bfloat16* __restrict__ Alo,
    const __nv_bfloat16* __restrict__ Bhi, const __nv_bfloat16* __restrict__ Blo,
    const float* __restrict__ bias, float* __restrict__ C,
    int M, int N, int K)
{
    extern __shared__ char smem[];
    const uint32_t sb = smem_u32(smem);
    const int tid = threadIdx.x;
    const int wid = tid >> 5;
    const int lane = tid & 31;
    const int bm = blockIdx.y * 128;
    const int bn = blockIdx.x * 128;
    const int wm = (wid & 1) * 64;
    const int wn = (wid >> 1) * 32;

    const __nv_bfloat16* gb[4] = {Ahi + (size_t)bm * K, Alo + (size_t)bm * K,
                                  Bhi + (size_t)bn * K, Blo + (size_t)bn * K};

    float acc[4][4][4];
#pragma unroll
    for (int mi = 0; mi < 4; mi++)
#pragma unroll
        for (int ni = 0; ni < 4; ni++)
#pragma unroll
            for (int e = 0; e < 4; e++) acc[mi][ni][e] = 0.f;

    const int nch = K / BK;
    const int row = tid >> 2;
    const int chunk = tid & 3;

    auto load_stage = [&](int buf, int k0) {
#pragma unroll
        for (int it = 0; it < 8; it++) {
            const int mat = it >> 1;
            const int r = ((it & 1) << 6) + row;
            const __nv_bfloat16* src = gb[mat] + (size_t)r * K + k0 + chunk * 8;
            const uint32_t dst = sb + buf * STAGEB + mat * MATB + r * ROWB + chunk * 16;
            cp16(dst, src);
        }
    };

    load_stage(0, 0);
    cp_commit();

    for (int ch = 0; ch < nch; ch++) {
        if (ch + 1 < nch) load_stage((ch + 1) & 1, (ch + 1) * BK);
        cp_commit();
        cp_wait1();
        __syncthreads();

        const uint32_t st = sb + (ch & 1) * STAGEB;
#pragma unroll
        for (int kk = 0; kk < 2; kk++) {
            uint32_t bh[4][2], bl[4][2];
            const uint32_t boff = (uint32_t)((wn + (lane & 7)) * ROWB
                                  + (kk * 16 + ((lane >> 3) & 1) * 8) * 2);
#pragma unroll
            for (int ni = 0; ni < 4; ni++) {
                ldmx2(bh[ni], st + 2 * MATB + boff + ni * 8 * ROWB);
                ldmx2(bl[ni], st + 3 * MATB + boff + ni * 8 * ROWB);
            }
            const uint32_t aoff = (uint32_t)((wm + (lane & 15)) * ROWB
                                  + (kk * 16 + (lane >> 4) * 8) * 2);
#pragma unroll
            for (int mi = 0; mi < 4; mi++) {
                uint32_t ah[4], al[4];
                ldmx4(ah, st + aoff + mi * 16 * ROWB);
                ldmx4(al, st + MATB + aoff + mi * 16 * ROWB);
#pragma unroll
                for (int ni = 0; ni < 4; ni++) {
                    mma_bf16(acc[mi][ni], ah, bh[ni]);
                    mma_bf16(acc[mi][ni], ah, bl[ni]);
                    mma_bf16(acc[mi][ni], al, bh[ni]);
                }
            }
        }
        __syncthreads();
    }

    const int g = lane >> 2;
    const int tg = lane & 3;
#pragma unroll
    for (int mi = 0; mi < 4; mi++) {
        const int r0 = bm + wm + mi * 16 + g;
#pragma unroll
        for (int ni = 0; ni < 4; ni++) {
            const int col = bn + wn + ni * 8 + tg * 2;
            const float2 bv = *(const float2*)(bias + col);
            float2 o0, o1;
            o0.x = acc[mi][ni][0] + bv.x; o0.y = acc[mi][ni][1] + bv.y;
            o1.x = acc[mi][ni][2] + bv.x; o1.y = acc[mi][ni][3] + bv.y;
            *(float2*)(C + (size_t)r0 * N + col) = o0;
            *(float2*)(C + (size_t)(r0 + 8) * N + col) = o1;
        }
    }
}

// ---------------------------------------------------------------------------
// Neighborhood attention, smem-tiled.
// Block = 8 adjacent pixels (along W) x 1 head; grid (10, 80, 8).
// k window stored transposed [dim][neighbor] (stride 99), v as [neighbor][dim].
// Lanes own neighbors in the score phase (no per-score shfl reductions).
// Epilogue emits bf16 hi/lo directly for the output-projection GEMM.
// ---------------------------------------------------------------------------
#define KST 99
#define O_Q 0
#define O_A 512
#define O_K 1024
#define O_V (1024 + 64 * KST)
#define ATTN_SMEM ((O_V + 98 * 64) * 4)

__global__ void __launch_bounds__(256) nat_attn(
    const float* __restrict__ qkv, const float* __restrict__ rpb,
    __nv_bfloat16* __restrict__ ahi, __nv_bfloat16* __restrict__ alo)
{
    extern __shared__ float sm[];
    const int tid = threadIdx.x;
    const int warp = tid >> 5;
    const int lane = tid & 31;
    const int jb = blockIdx.x * 8;
    const int i = blockIdx.y;
    const int h = blockIdx.z;

    const int j = jb + warp;
    const int pix = i * HWDIM + j;

    const int sh = min(max(i - 3, 0), HWDIM - KWIN);
    const int sw = min(max(j - 3, 0), HWDIM - KWIN);
    const int cmin = min(max(jb - 3, 0), HWDIM - KWIN);            // sw of warp 0
    const int cmax = min(max(jb + 7 - 3, 0), HWDIM - KWIN) + 6;    // last col
    const int wb = cmax - cmin + 1;                                 // <= 14
    const int swloc = sw - cmin;

    // --- q load (scaled) ---
    {
        const float2 qv = ((const float2*)(qkv + (size_t)pix * QKVN + h * HD))[lane];
        float2 qs; qs.x = qv.x * 0.125f; qs.y = qv.y * 0.125f;
        *(float2*)&sm[O_Q + warp * 64 + 2 * lane] = qs;
    }

    // --- cooperative k/v window load: 7 x wb segments x {k,v} ---
    for (int s = warp; s < 196; s += 8) {
        const int kv = s & 1;
        const int ss = s >> 1;
        const int a = ss / 14;
        const int c = ss % 14;
        if (c >= wb) continue;
        const float* gp = qkv + (size_t)((sh + a) * HWDIM + cmin + c) * QKVN
                        + (kv ? 2 * DIM : DIM) + h * HD;
        const int nbr = a * 14 + c;
        if (kv == 0) {
            sm[O_K + lane * KST + nbr]        = gp[lane];
            sm[O_K + (lane + 32) * KST + nbr] = gp[lane + 32];
        } else {
            *(float2*)&sm[O_V + nbr * 64 + 2 * lane] = ((const float2*)gp)[lane];
        }
    }
    __syncthreads();

    // --- scores: lane owns neighbors t0=lane, t1=lane+32 ---
    const int a0 = lane / 7,        c0 = lane % 7;
    const int a1 = (lane + 32) / 7, c1 = (lane + 32) % 7;
    const bool v1 = (lane + 32) < 49;
    const int nbr0 = a0 * 14 + swloc + c0;
    const int nbr1 = v1 ? (a1 * 14 + swloc + c1) : nbr0;

    float s0 = 0.f, s1 = 0.f;
    const float* qs = &sm[O_Q + warp * 64];
    const float* ks = &sm[O_K];
#pragma unroll
    for (int d = 0; d < 64; d++) {
        const float qd = qs[d];
        s0 = fmaf(qd, ks[d * KST + nbr0], s0);
        s1 = fmaf(qd, ks[d * KST + nbr1], s1);
    }
    const float* rp = rpb + h * 169 + (sh - i + 6) * 13 + (sw - j + 6);
    s0 += rp[a0 * 13 + c0];
    s1 = v1 ? (s1 + rp[a1 * 13 + c1]) : -1e30f;

    // --- softmax across the warp ---
    float m = fmaxf(s0, s1);
#pragma unroll
    for (int o = 16; o; o >>= 1)
        m = fmaxf(m, __shfl_xor_sync(0xffffffffu, m, o));
    float e0 = __expf(s0 - m);
    float e1 = v1 ? __expf(s1 - m) : 0.f;
    float sum = e0 + e1;
#pragma unroll
    for (int o = 16; o; o >>= 1)
        sum += __shfl_xor_sync(0xffffffffu, sum, o);
    const float inv = __fdividef(1.f, sum);

    float* as = &sm[O_A + warp * 64];
    as[lane] = e0 * inv;
    if (v1) as[lane + 32] = e1 * inv;
    __syncwarp();

    // --- AV: lane owns dims 2*lane, 2*lane+1 ---
    float ax = 0.f, ay = 0.f;
    const float* vs = &sm[O_V + swloc * 64 + 2 * lane];
#pragma unroll
    for (int t = 0; t < 49; t++) {
        const int a = t / 7, c = t % 7;
        const float at = as[t];
        const float2 vv = *(const float2*)&vs[(a * 14 + c) * 64];
        ax = fmaf(at, vv.x, ax);
        ay = fmaf(at, vv.y, ay);
    }

    // --- fused bf16 hi/lo epilogue ---
    __nv_bfloat16 hx = __float2bfloat16(ax);
    __nv_bfloat16 hy = __float2bfloat16(ay);
    __nv_bfloat16 lx = __float2bfloat16(ax - __bfloat162float(hx));
    __nv_bfloat16 ly = __float2bfloat16(ay - __bfloat162float(hy));
    const size_t oidx = (size_t)pix * DIM + h * HD + 2 * lane;
    __nv_bfloat162 ph(hx, hy), pl(lx, ly);
    *(__nv_bfloat162*)(ahi + oidx) = ph;
    *(__nv_bfloat162*)(alo + oidx) = pl;
}

// ---------------------------------------------------------------------------
extern "C" void kernel_launch(void* const* d_in, const int* in_sizes, int n_in,
                              void* d_out, int out_size)
{
    const float* x      = (const float*)d_in[0];
    const float* qkv_w  = (const float*)d_in[1];
    const float* qkv_b  = (const float*)d_in[2];
    const float* rpb    = (const float*)d_in[3];
    const float* proj_w = (const float*)d_in[4];
    const float* proj_b = (const float*)d_in[5];
    float* out = (float*)d_out;

    float *qkv;
    __nv_bfloat16 *xhi, *xlo, *w1hi, *w1lo, *ahi, *alo, *w2hi, *w2lo;
    cudaGetSymbolAddress((void**)&qkv, g_qkv);
    cudaGetSymbolAddress((void**)&xhi, g_xhi);
    cudaGetSymbolAddress((void**)&xlo, g_xlo);
    cudaGetSymbolAddress((void**)&w1hi, g_w1hi);
    cudaGetSymbolAddress((void**)&w1lo, g_w1lo);
    cudaGetSymbolAddress((void**)&ahi, g_ahi);
    cudaGetSymbolAddress((void**)&alo, g_alo);
    cudaGetSymbolAddress((void**)&w2hi, g_w2hi);
    cudaGetSymbolAddress((void**)&w2lo, g_w2lo);

    cudaFuncSetAttribute(gemm_bf16x3,
                         cudaFuncAttributeMaxDynamicSharedMemorySize, GEMM_SMEM);
    cudaFuncSetAttribute(nat_attn,
                         cudaFuncAttributeMaxDynamicSharedMemorySize, ATTN_SMEM);

    // 0) Split inputs into bf16 hi/lo
    cvt_hilo<<<NPIX * DIM / 1024, 256>>>(x, xhi, xlo);
    cvt_hilo<<<QKVN * DIM / 1024, 256>>>(qkv_w, w1hi, w1lo);
    cvt_hilo<<<DIM * DIM / 1024, 256>>>(proj_w, w2hi, w2lo);

    // 1) QKV projection
    gemm_bf16x3<<<dim3(QKVN / 128, NPIX / 128), 256, GEMM_SMEM>>>(
        xhi, xlo, w1hi, w1lo, qkv_b, qkv, NPIX, QKVN, DIM);

    // 2) Neighborhood attention (emits bf16 hi/lo directly)
    nat_attn<<<dim3(HWDIM / 8, HWDIM, NHEAD), 256, ATTN_SMEM>>>(
        qkv, rpb, ahi, alo);

    // 3) Output projection
    gemm_bf16x3<<<dim3(DIM / 128, NPIX / 128), 256, GEMM_SMEM>>>(
        ahi, alo, w2hi, w2lo, proj_b, out, NPIX, DIM, DIM);
}

// round 5
// speedup vs baseline: 1.0873x; 1.0873x over previous
#include <cuda_runtime.h>
#include <cuda_bf16.h>
#include <cstdint>
#include <math.h>

// Problem constants
#define HWDIM 80
#define NPIX  6400
#define DIM   512
#define QKVN  1536
#define NHEAD 8
#define HD    64
#define KWIN  7

// Scratch (allocation-free rule: __device__ globals)
__device__ float g_qkv[(size_t)NPIX * QKVN];
__device__ __nv_bfloat16 g_xhi[(size_t)NPIX * DIM];
__device__ __nv_bfloat16 g_xlo[(size_t)NPIX * DIM];
__device__ __nv_bfloat16 g_w1hi[(size_t)QKVN * DIM];
__device__ __nv_bfloat16 g_w1lo[(size_t)QKVN * DIM];
__device__ __nv_bfloat16 g_ahi[(size_t)NPIX * DIM];
__device__ __nv_bfloat16 g_alo[(size_t)NPIX * DIM];
__device__ __nv_bfloat16 g_w2hi[(size_t)DIM * DIM];
__device__ __nv_bfloat16 g_w2lo[(size_t)DIM * DIM];

#define N_X  (NPIX * DIM)    // 3276800
#define N_W1 (QKVN * DIM)    // 786432
#define N_W2 (DIM * DIM)     // 262144

// ---------------------------------------------------------------------------
// fp32 -> bf16 hi/lo split for all three inputs in one launch.
// ---------------------------------------------------------------------------
__global__ void __launch_bounds__(256) cvt_all(
    const float* __restrict__ x, const float* __restrict__ w1,
    const float* __restrict__ w2,
    __nv_bfloat16* __restrict__ xhi, __nv_bfloat16* __restrict__ xlo,
    __nv_bfloat16* __restrict__ w1hi, __nv_bfloat16* __restrict__ w1lo,
    __nv_bfloat16* __restrict__ w2hi, __nv_bfloat16* __restrict__ w2lo)
{
    int i = (blockIdx.x * 256 + threadIdx.x) * 4;
    const float* src;
    __nv_bfloat16 *hi, *lo;
    if (i < N_X)              { src = x + i;            hi = xhi + i;            lo = xlo + i; }
    else if (i < N_X + N_W1)  { i -= N_X;  src = w1 + i; hi = w1hi + i;          lo = w1lo + i; }
    else                      { i -= N_X + N_W1; src = w2 + i; hi = w2hi + i;    lo = w2lo + i; }

    float4 v = *(const float4*)src;
    float f[4] = {v.x, v.y, v.z, v.w};
    __nv_bfloat16 h[4], l[4];
#pragma unroll
    for (int k = 0; k < 4; k++) {
        h[k] = __float2bfloat16(f[k]);
        l[k] = __float2bfloat16(f[k] - __bfloat162float(h[k]));
    }
    uint2 ph, pl;
    {
        __nv_bfloat162 t;
        t = __nv_bfloat162(h[0], h[1]); ph.x = *(uint32_t*)&t;
        t = __nv_bfloat162(h[2], h[3]); ph.y = *(uint32_t*)&t;
        t = __nv_bfloat162(l[0], l[1]); pl.x = *(uint32_t*)&t;
        t = __nv_bfloat162(l[2], l[3]); pl.y = *(uint32_t*)&t;
    }
    *(uint2*)hi = ph;
    *(uint2*)lo = pl;
}

// ---------------------------------------------------------------------------
// mma.sync bf16 GEMM (3xBF16 compensated): C[M,N] = A[M,K] @ B[N,K]^T + bias
// 128x64 CTA tile, BK=32, cp.async double buffer, 3 CTAs/SM.
// 256 threads = 8 warps in 4(m) x 2(n); warp tile 32x32.
// ---------------------------------------------------------------------------
#define BK 32
#define ROWB 80                    // padded row stride (32 bf16 + 16B pad)
#define AMATB (128 * ROWB)         // 10240
#define BMATB (64 * ROWB)          // 5120
#define STAGEB (2 * AMATB + 2 * BMATB)   // 30720
#define GEMM_SMEM (2 * STAGEB)           // 61440

__device__ __forceinline__ uint32_t smem_u32(const void* p) {
    uint32_t a;
    asm("{ .reg .u64 t; cvta.to.shared.u64 t, %1; cvt.u32.u64 %0, t; }"
        : "=r"(a) : "l"(p));
    return a;
}
__device__ __forceinline__ void cp16(uint32_t dst, const void* src) {
    asm volatile("cp.async.cg.shared.global [%0], [%1], 16;"
                 :: "r"(dst), "l"(src));
}
__device__ __forceinline__ void cp_commit() {
    asm volatile("cp.async.commit_group;" ::: "memory");
}
__device__ __forceinline__ void cp_wait1() {
    asm volatile("cp.async.wait_group 1;" ::: "memory");
}
__device__ __forceinline__ void ldmx4(uint32_t* r, uint32_t addr) {
    asm volatile("ldmatrix.sync.aligned.m8n8.x4.shared.b16 {%0,%1,%2,%3}, [%4];"
                 : "=r"(r[0]), "=r"(r[1]), "=r"(r[2]), "=r"(r[3]) : "r"(addr));
}
__device__ __forceinline__ void ldmx2(uint32_t* r, uint32_t addr) {
    asm volatile("ldmatrix.sync.aligned.m8n8.x2.shared.b16 {%0,%1}, [%2];"
                 : "=r"(r[0]), "=r"(r[1]) : "r"(addr));
}
__device__ __forceinline__ void mma_bf16(float* c, const uint32_t* a, const uint32_t* b) {
    asm volatile(
        "mma.sync.aligned.m16n8k16.row.col.f32.bf16.bf16.f32 "
        "{%0,%1,%2,%3}, {%4,%5,%6,%7}, {%8,%9}, {%0,%1,%2,%3};"
        : "+f"(c[0]), "+f"(c[1]), "+f"(c[2]), "+f"(c[3])
        : "r"(a[0]), "r"(a[1]), "r"(a[2]), "r"(a[3]), "r"(b[0]), "r"(b[1]));
}

__global__ void __launch_bounds__(256, 3) gemm_bf16x3(
    const __nv_bfloat16* __restrict__ Ahi, const __nv_bfloat16* __restrict__ Alo,
    const __nv_bfloat16* __restrict__ Bhi, const __nv_bfloat16* __restrict__ Blo,
    const float* __restrict__ bias, float* __restrict__ C,
    int M, int N, int K)
{
    extern __shared__ char smem[];
    const uint32_t sb = smem_u32(smem);
    const int tid = threadIdx.x;
    const int wid = tid >> 5;
    const int lane = tid & 31;
    const int bm = blockIdx.y * 128;
    const int bn = blockIdx.x * 64;
    const int wm = (wid & 3) * 32;    // warp m offset
    const int wn = (wid >> 2) * 32;   // warp n offset

    const __nv_bfloat16* gA[2] = {Ahi + (size_t)bm * K, Alo + (size_t)bm * K};
    const __nv_bfloat16* gB[2] = {Bhi + (size_t)bn * K, Blo + (size_t)bn * K};

    float acc[2][4][4];
#pragma unroll
    for (int mi = 0; mi < 2; mi++)
#pragma unroll
        for (int ni = 0; ni < 4; ni++)
#pragma unroll
            for (int e = 0; e < 4; e++) acc[mi][ni][e] = 0.f;

    const int nch = K / BK;
    const int row = tid >> 2;      // 0..63
    const int chunk = tid & 3;     // 16B chunk within 64B row

    // stage = 1536 x 16B; 6 cp16 per thread:
    //   A(hi,lo): 128 rows x 4 chunks = 512 each (2 iters of 256)
    //   B(hi,lo): 64 rows x 4 chunks  = 256 each (1 iter)
    auto load_stage = [&](int buf, int k0) {
        const uint32_t st = sb + buf * STAGEB;
#pragma unroll
        for (int m = 0; m < 2; m++) {     // hi / lo
#pragma unroll
            for (int rb = 0; rb < 2; rb++) {
                const int r = rb * 64 + row;
                cp16(st + m * AMATB + r * ROWB + chunk * 16,
                     gA[m] + (size_t)r * K + k0 + chunk * 8);
            }
            cp16(st + 2 * AMATB + m * BMATB + row * ROWB + chunk * 16,
                 gB[m] + (size_t)row * K + k0 + chunk * 8);
        }
    };

    load_stage(0, 0);
    cp_commit();

    for (int ch = 0; ch < nch; ch++) {
        if (ch + 1 < nch) load_stage((ch + 1) & 1, (ch + 1) * BK);
        cp_commit();
        cp_wait1();
        __syncthreads();

        const uint32_t st = sb + (ch & 1) * STAGEB;
#pragma unroll
        for (int kk = 0; kk < 2; kk++) {
            uint32_t bh[4][2], bl[4][2];
            const uint32_t boff = (uint32_t)((wn + (lane & 7)) * ROWB
                                  + (kk * 16 + ((lane >> 3) & 1) * 8) * 2);
#pragma unroll
            for (int ni = 0; ni < 4; ni++) {
                ldmx2(bh[ni], st + 2 * AMATB + boff + ni * 8 * ROWB);
                ldmx2(bl[ni], st + 2 * AMATB + BMATB + boff + ni * 8 * ROWB);
            }
            const uint32_t aoff = (uint32_t)((wm + (lane & 15)) * ROWB
                                  + (kk * 16 + (lane >> 4) * 8) * 2);
#pragma unroll
            for (int mi = 0; mi < 2; mi++) {
                uint32_t ah[4], al[4];
                ldmx4(ah, st + aoff + mi * 16 * ROWB);
                ldmx4(al, st + AMATB + aoff + mi * 16 * ROWB);
#pragma unroll
                for (int ni = 0; ni < 4; ni++) {
                    mma_bf16(acc[mi][ni], ah, bh[ni]);
                    mma_bf16(acc[mi][ni], ah, bl[ni]);
                    mma_bf16(acc[mi][ni], al, bh[ni]);
                }
            }
        }
        __syncthreads();
    }

    const int g = lane >> 2;
    const int tg = lane & 3;
#pragma unroll
    for (int mi = 0; mi < 2; mi++) {
        const int r0 = bm + wm + mi * 16 + g;
#pragma unroll
        for (int ni = 0; ni < 4; ni++) {
            const int col = bn + wn + ni * 8 + tg * 2;
            const float2 bv = *(const float2*)(bias + col);
            float2 o0, o1;
            o0.x = acc[mi][ni][0] + bv.x; o0.y = acc[mi][ni][1] + bv.y;
            o1.x = acc[mi][ni][2] + bv.x; o1.y = acc[mi][ni][3] + bv.y;
            *(float2*)(C + (size_t)r0 * N + col) = o0;
            *(float2*)(C + (size_t)(r0 + 8) * N + col) = o1;
        }
    }
}

// ---------------------------------------------------------------------------
// Neighborhood attention: one warp per (pixel, head) [R3 structure].
// Fused bf16 hi/lo epilogue feeds the output-projection GEMM directly.
// ---------------------------------------------------------------------------
__global__ void __launch_bounds__(256) nat_attn(
    const float* __restrict__ qkv, const float* __restrict__ rpb,
    __nv_bfloat16* __restrict__ ahi, __nv_bfloat16* __restrict__ alo)
{
    const int warp = threadIdx.x >> 5;
    const int lane = threadIdx.x & 31;
    const int j = blockIdx.x * 8 + warp;
    const int i = blockIdx.y;
    const int h = blockIdx.z;
    const int pix = i * HWDIM + j;

    const int sh = min(max(i - 3, 0), HWDIM - KWIN);
    const int sw = min(max(j - 3, 0), HWDIM - KWIN);

    const float2 qv = ((const float2*)(qkv + (size_t)pix * QKVN + h * HD))[lane];
    const float qx = qv.x * 0.125f;
    const float qy = qv.y * 0.125f;

    const float* rp = rpb + h * 169 + (sh - i + 6) * 13 + (sw - j + 6);

    float loc0 = -1e30f, loc1 = -1e30f;

#pragma unroll
    for (int a = 0; a < KWIN; a++) {
        const float* kbase = qkv + (size_t)((sh + a) * HWDIM + sw) * QKVN + DIM + h * HD;
#pragma unroll
        for (int c = 0; c < KWIN; c++) {
            float2 kv = ((const float2*)(kbase + (size_t)c * QKVN))[lane];
            float s = qx * kv.x + qy * kv.y;
#pragma unroll
            for (int o = 16; o; o >>= 1)
                s += __shfl_xor_sync(0xffffffffu, s, o);
            s += rp[a * 13 + c];
            const int t = a * KWIN + c;
            if ((t & 31) == lane) {
                if (t < 32) loc0 = s; else loc1 = s;
            }
        }
    }

    float m = fmaxf(loc0, loc1);
#pragma unroll
    for (int o = 16; o; o >>= 1)
        m = fmaxf(m, __shfl_xor_sync(0xffffffffu, m, o));
    float e0 = __expf(loc0 - m);
    float e1 = __expf(loc1 - m);
    float sum = e0 + e1;
#pragma unroll
    for (int o = 16; o; o >>= 1)
        sum += __shfl_xor_sync(0xffffffffu, sum, o);
    const float inv = __fdividef(1.f, sum);
    e0 *= inv;
    e1 *= inv;

    float accx = 0.f, accy = 0.f;
#pragma unroll
    for (int a = 0; a < KWIN; a++) {
        const float* vbase = qkv + (size_t)((sh + a) * HWDIM + sw) * QKVN + 2 * DIM + h * HD;
#pragma unroll
        for (int c = 0; c < KWIN; c++) {
            const int t = a * KWIN + c;
            float at = __shfl_sync(0xffffffffu, (t < 32) ? e0 : e1, t & 31);
            float2 vv = ((const float2*)(vbase + (size_t)c * QKVN))[lane];
            accx = fmaf(at, vv.x, accx);
            accy = fmaf(at, vv.y, accy);
        }
    }

    // fused bf16 hi/lo epilogue
    __nv_bfloat16 hx = __float2bfloat16(accx);
    __nv_bfloat16 hy = __float2bfloat16(accy);
    __nv_bfloat16 lx = __float2bfloat16(accx - __bfloat162float(hx));
    __nv_bfloat16 ly = __float2bfloat16(accy - __bfloat162float(hy));
    const size_t oidx = (size_t)pix * DIM + h * HD + 2 * lane;
    __nv_bfloat162 ph(hx, hy), pl(lx, ly);
    *(__nv_bfloat162*)(ahi + oidx) = ph;
    *(__nv_bfloat162*)(alo + oidx) = pl;
}

// ---------------------------------------------------------------------------
extern "C" void kernel_launch(void* const* d_in, const int* in_sizes, int n_in,
                              void* d_out, int out_size)
{
    const float* x      = (const float*)d_in[0];
    const float* qkv_w  = (const float*)d_in[1];
    const float* qkv_b  = (const float*)d_in[2];
    const float* rpb    = (const float*)d_in[3];
    const float* proj_w = (const float*)d_in[4];
    const float* proj_b = (const float*)d_in[5];
    float* out = (float*)d_out;

    float *qkv;
    __nv_bfloat16 *xhi, *xlo, *w1hi, *w1lo, *ahi, *alo, *w2hi, *w2lo;
    cudaGetSymbolAddress((void**)&qkv, g_qkv);
    cudaGetSymbolAddress((void**)&xhi, g_xhi);
    cudaGetSymbolAddress((void**)&xlo, g_xlo);
    cudaGetSymbolAddress((void**)&w1hi, g_w1hi);
    cudaGetSymbolAddress((void**)&w1lo, g_w1lo);
    cudaGetSymbolAddress((void**)&ahi, g_ahi);
    cudaGetSymbolAddress((void**)&alo, g_alo);
    cudaGetSymbolAddress((void**)&w2hi, g_w2hi);
    cudaGetSymbolAddress((void**)&w2lo, g_w2lo);

    cudaFuncSetAttribute(gemm_bf16x3,
                         cudaFuncAttributeMaxDynamicSharedMemorySize, GEMM_SMEM);

    // 0) Split all fp32 inputs into bf16 hi/lo (one launch)
    cvt_all<<<(N_X + N_W1 + N_W2) / 1024, 256>>>(
        x, qkv_w, proj_w, xhi, xlo, w1hi, w1lo, w2hi, w2lo);

    // 1) QKV projection: [6400,1536] = x @ qkv_w^T + qkv_b
    gemm_bf16x3<<<dim3(QKVN / 64, NPIX / 128), 256, GEMM_SMEM>>>(
        xhi, xlo, w1hi, w1lo, qkv_b, qkv, NPIX, QKVN, DIM);

    // 2) Neighborhood attention (emits bf16 hi/lo directly)
    nat_attn<<<dim3(HWDIM / 8, HWDIM, NHEAD), 256>>>(qkv, rpb, ahi, alo);

    // 3) Output projection
    gemm_bf16x3<<<dim3(DIM / 64, NPIX / 128), 256, GEMM_SMEM>>>(
        ahi, alo, w2hi, w2lo, proj_b, out, NPIX, DIM, DIM);
}

// round 6
// speedup vs baseline: 1.1135x; 1.0240x over previous
#include <cuda_runtime.h>
#include <cuda_bf16.h>
#include <cstdint>
#include <math.h>

// Problem constants
#define HWDIM 80
#define NPIX  6400
#define DIM   512
#define QKVN  1536
#define NHEAD 8
#define HD    64
#define KWIN  7

// Scratch (allocation-free rule: __device__ globals)
__device__ float g_qkv[(size_t)NPIX * QKVN];
__device__ __nv_bfloat16 g_xhi[(size_t)NPIX * DIM];
__device__ __nv_bfloat16 g_xlo[(size_t)NPIX * DIM];
__device__ __nv_bfloat16 g_w1hi[(size_t)QKVN * DIM];
__device__ __nv_bfloat16 g_w1lo[(size_t)QKVN * DIM];
__device__ __nv_bfloat16 g_ahi[(size_t)NPIX * DIM];
__device__ __nv_bfloat16 g_alo[(size_t)NPIX * DIM];
__device__ __nv_bfloat16 g_w2hi[(size_t)DIM * DIM];
__device__ __nv_bfloat16 g_w2lo[(size_t)DIM * DIM];

#define N_X  (NPIX * DIM)
#define N_W1 (QKVN * DIM)
#define N_W2 (DIM * DIM)

// ---------------------------------------------------------------------------
// fp32 -> bf16 hi/lo split for all three inputs in one launch.
// ---------------------------------------------------------------------------
__global__ void __launch_bounds__(256) cvt_all(
    const float* __restrict__ x, const float* __restrict__ w1,
    const float* __restrict__ w2,
    __nv_bfloat16* __restrict__ xhi, __nv_bfloat16* __restrict__ xlo,
    __nv_bfloat16* __restrict__ w1hi, __nv_bfloat16* __restrict__ w1lo,
    __nv_bfloat16* __restrict__ w2hi, __nv_bfloat16* __restrict__ w2lo)
{
    int i = (blockIdx.x * 256 + threadIdx.x) * 4;
    const float* src;
    __nv_bfloat16 *hi, *lo;
    if (i < N_X)              { src = x + i;             hi = xhi + i;  lo = xlo + i; }
    else if (i < N_X + N_W1)  { i -= N_X;  src = w1 + i; hi = w1hi + i; lo = w1lo + i; }
    else                      { i -= N_X + N_W1; src = w2 + i; hi = w2hi + i; lo = w2lo + i; }

    float4 v = *(const float4*)src;
    float f[4] = {v.x, v.y, v.z, v.w};
    __nv_bfloat16 h[4], l[4];
#pragma unroll
    for (int k = 0; k < 4; k++) {
        h[k] = __float2bfloat16(f[k]);
        l[k] = __float2bfloat16(f[k] - __bfloat162float(h[k]));
    }
    uint2 ph, pl;
    {
        __nv_bfloat162 t;
        t = __nv_bfloat162(h[0], h[1]); ph.x = *(uint32_t*)&t;
        t = __nv_bfloat162(h[2], h[3]); ph.y = *(uint32_t*)&t;
        t = __nv_bfloat162(l[0], l[1]); pl.x = *(uint32_t*)&t;
        t = __nv_bfloat162(l[2], l[3]); pl.y = *(uint32_t*)&t;
    }
    *(uint2*)hi = ph;
    *(uint2*)lo = pl;
}

// ---------------------------------------------------------------------------
// mma.sync bf16 GEMM (3xBF16 compensated): C[M,N] = A[M,K] @ B[N,K]^T + bias
// 128x64 CTA tile, BK=32, 3-stage cp.async pipeline, ONE syncthreads/chunk.
// 256 threads = 8 warps in 4(m) x 2(n); warp tile 32x32.
// ---------------------------------------------------------------------------
#define BK 32
#define ROWB 80                          // padded row stride (32 bf16 + 16B pad)
#define AMATB (128 * ROWB)               // 10240
#define BMATB (64 * ROWB)                // 5120
#define STAGEB (2 * AMATB + 2 * BMATB)   // 30720
#define GEMM_SMEM (3 * STAGEB)           // 92160

__device__ __forceinline__ uint32_t smem_u32(const void* p) {
    uint32_t a;
    asm("{ .reg .u64 t; cvta.to.shared.u64 t, %1; cvt.u32.u64 %0, t; }"
        : "=r"(a) : "l"(p));
    return a;
}
__device__ __forceinline__ void cp16(uint32_t dst, const void* src) {
    asm volatile("cp.async.cg.shared.global [%0], [%1], 16;"
                 :: "r"(dst), "l"(src));
}
__device__ __forceinline__ void cp_commit() {
    asm volatile("cp.async.commit_group;" ::: "memory");
}
__device__ __forceinline__ void cp_wait1() {
    asm volatile("cp.async.wait_group 1;" ::: "memory");
}
__device__ __forceinline__ void cp_wait0() {
    asm volatile("cp.async.wait_group 0;" ::: "memory");
}
__device__ __forceinline__ void ldmx4(uint32_t* r, uint32_t addr) {
    asm volatile("ldmatrix.sync.aligned.m8n8.x4.shared.b16 {%0,%1,%2,%3}, [%4];"
                 : "=r"(r[0]), "=r"(r[1]), "=r"(r[2]), "=r"(r[3]) : "r"(addr));
}
__device__ __forceinline__ void mma_bf16(float* c, const uint32_t* a, const uint32_t* b) {
    asm volatile(
        "mma.sync.aligned.m16n8k16.row.col.f32.bf16.bf16.f32 "
        "{%0,%1,%2,%3}, {%4,%5,%6,%7}, {%8,%9}, {%0,%1,%2,%3};"
        : "+f"(c[0]), "+f"(c[1]), "+f"(c[2]), "+f"(c[3])
        : "r"(a[0]), "r"(a[1]), "r"(a[2]), "r"(a[3]), "r"(b[0]), "r"(b[1]));
}

__global__ void __launch_bounds__(256, 2) gemm_bf16x3(
    const __nv_bfloat16* __restrict__ Ahi, const __nv_bfloat16* __restrict__ Alo,
    const __nv_bfloat16* __restrict__ Bhi, const __nv_bfloat16* __restrict__ Blo,
    const float* __restrict__ bias, float* __restrict__ C,
    int M, int N, int K)
{
    extern __shared__ char smem[];
    const uint32_t sb = smem_u32(smem);
    const int tid = threadIdx.x;
    const int wid = tid >> 5;
    const int lane = tid & 31;
    const int bm = blockIdx.y * 128;
    const int bn = blockIdx.x * 64;
    const int wm = (wid & 3) * 32;
    const int wn = (wid >> 2) * 32;

    const __nv_bfloat16* gA[2] = {Ahi + (size_t)bm * K, Alo + (size_t)bm * K};
    const __nv_bfloat16* gB[2] = {Bhi + (size_t)bn * K, Blo + (size_t)bn * K};

    float acc[2][4][4];
#pragma unroll
    for (int mi = 0; mi < 2; mi++)
#pragma unroll
        for (int ni = 0; ni < 4; ni++)
#pragma unroll
            for (int e = 0; e < 4; e++) acc[mi][ni][e] = 0.f;

    const int nch = K / BK;          // 16
    const int row = tid >> 2;        // 0..63
    const int chunk = tid & 3;       // 16B chunk within the 64B k-row

    auto load_stage = [&](int buf, int k0) {
        const uint32_t st = sb + buf * STAGEB;
#pragma unroll
        for (int m = 0; m < 2; m++) {
#pragma unroll
            for (int rb = 0; rb < 2; rb++) {
                const int r = rb * 64 + row;
                cp16(st + m * AMATB + r * ROWB + chunk * 16,
                     gA[m] + (size_t)r * K + k0 + chunk * 8);
            }
            cp16(st + 2 * AMATB + m * BMATB + row * ROWB + chunk * 16,
                 gB[m] + (size_t)row * K + k0 + chunk * 8);
        }
    };

    load_stage(0, 0);      cp_commit();
    load_stage(1, BK);     cp_commit();

    // ldmatrix lane mappings
    //   A (x4): rows = wm + (lane & 15), k-half = (lane >> 4) * 8
    //   B (x4, ni-pair): nrow = (lane&7) + ((lane>>4)&1)*8, koff = ((lane>>3)&1)*8
    const int a_r  = wm + (lane & 15);
    const int a_k  = (lane >> 4) * 8;
    const int b_nr = (lane & 7) + ((lane >> 4) & 1) * 8;
    const int b_k  = ((lane >> 3) & 1) * 8;

    int buf = 0;
    for (int ch = 0; ch < nch; ch++) {
        if (ch + 1 < nch) cp_wait1(); else cp_wait0();
        __syncthreads();
        const int nb = ch + 2;
        if (nb < nch) {
            int b3 = nb - (nb / 3) * 3;
            load_stage(b3, nb * BK);
            cp_commit();
        }

        const uint32_t st = sb + buf * STAGEB;
#pragma unroll
        for (int kk = 0; kk < 2; kk++) {
            // B fragments: pairs (0,1),(2,3) x {hi,lo} = 4 ldmx4
            uint32_t bh[4][2], bl[4][2];
            const uint32_t bbase = st + 2 * AMATB
                + (uint32_t)((wn + b_nr) * ROWB + (kk * 16 + b_k) * 2);
#pragma unroll
            for (int p = 0; p < 2; p++) {
                uint32_t rh[4], rl[4];
                ldmx4(rh, bbase + p * 16 * ROWB);
                ldmx4(rl, bbase + BMATB + p * 16 * ROWB);
                bh[2 * p][0] = rh[0]; bh[2 * p][1] = rh[1];
                bh[2 * p + 1][0] = rh[2]; bh[2 * p + 1][1] = rh[3];
                bl[2 * p][0] = rl[0]; bl[2 * p][1] = rl[1];
                bl[2 * p + 1][0] = rl[2]; bl[2 * p + 1][1] = rl[3];
            }
            const uint32_t abase = st
                + (uint32_t)(a_r * ROWB + (kk * 16 + a_k) * 2);
#pragma unroll
            for (int mi = 0; mi < 2; mi++) {
                uint32_t ah[4], al[4];
                ldmx4(ah, abase + mi * 16 * ROWB);
                ldmx4(al, abase + AMATB + mi * 16 * ROWB);
#pragma unroll
                for (int ni = 0; ni < 4; ni++) {
                    mma_bf16(acc[mi][ni], ah, bh[ni]);
                    mma_bf16(acc[mi][ni], ah, bl[ni]);
                    mma_bf16(acc[mi][ni], al, bh[ni]);
                }
            }
        }
        buf = (buf == 2) ? 0 : buf + 1;
    }

    const int g = lane >> 2;
    const int tg = lane & 3;
#pragma unroll
    for (int mi = 0; mi < 2; mi++) {
        const int r0 = bm + wm + mi * 16 + g;
#pragma unroll
        for (int ni = 0; ni < 4; ni++) {
            const int col = bn + wn + ni * 8 + tg * 2;
            const float2 bv = *(const float2*)(bias + col);
            float2 o0, o1;
            o0.x = acc[mi][ni][0] + bv.x; o0.y = acc[mi][ni][1] + bv.y;
            o1.x = acc[mi][ni][2] + bv.x; o1.y = acc[mi][ni][3] + bv.y;
            *(float2*)(C + (size_t)r0 * N + col) = o0;
            *(float2*)(C + (size_t)(r0 + 8) * N + col) = o1;
        }
    }
}

// ---------------------------------------------------------------------------
// Neighborhood attention: one warp per (pixel, head) [R3 structure].
// Fused bf16 hi/lo epilogue feeds the output-projection GEMM directly.
// ---------------------------------------------------------------------------
__global__ void __launch_bounds__(256) nat_attn(
    const float* __restrict__ qkv, const float* __restrict__ rpb,
    __nv_bfloat16* __restrict__ ahi, __nv_bfloat16* __restrict__ alo)
{
    const int warp = threadIdx.x >> 5;
    const int lane = threadIdx.x & 31;
    const int j = blockIdx.x * 8 + warp;
    const int i = blockIdx.y;
    const int h = blockIdx.z;
    const int pix = i * HWDIM + j;

    const int sh = min(max(i - 3, 0), HWDIM - KWIN);
    const int sw = min(max(j - 3, 0), HWDIM - KWIN);

    const float2 qv = ((const float2*)(qkv + (size_t)pix * QKVN + h * HD))[lane];
    const float qx = qv.x * 0.125f;
    const float qy = qv.y * 0.125f;

    const float* rp = rpb + h * 169 + (sh - i + 6) * 13 + (sw - j + 6);

    float loc0 = -1e30f, loc1 = -1e30f;

#pragma unroll
    for (int a = 0; a < KWIN; a++) {
        const float* kbase = qkv + (size_t)((sh + a) * HWDIM + sw) * QKVN + DIM + h * HD;
#pragma unroll
        for (int c = 0; c < KWIN; c++) {
            float2 kv = ((const float2*)(kbase + (size_t)c * QKVN))[lane];
            float s = qx * kv.x + qy * kv.y;
#pragma unroll
            for (int o = 16; o; o >>= 1)
                s += __shfl_xor_sync(0xffffffffu, s, o);
            s += rp[a * 13 + c];
            const int t = a * KWIN + c;
            if ((t & 31) == lane) {
                if (t < 32) loc0 = s; else loc1 = s;
            }
        }
    }

    float m = fmaxf(loc0, loc1);
#pragma unroll
    for (int o = 16; o; o >>= 1)
        m = fmaxf(m, __shfl_xor_sync(0xffffffffu, m, o));
    float e0 = __expf(loc0 - m);
    float e1 = __expf(loc1 - m);
    float sum = e0 + e1;
#pragma unroll
    for (int o = 16; o; o >>= 1)
        sum += __shfl_xor_sync(0xffffffffu, sum, o);
    const float inv = __fdividef(1.f, sum);
    e0 *= inv;
    e1 *= inv;

    float accx = 0.f, accy = 0.f;
#pragma unroll
    for (int a = 0; a < KWIN; a++) {
        const float* vbase = qkv + (size_t)((sh + a) * HWDIM + sw) * QKVN + 2 * DIM + h * HD;
#pragma unroll
        for (int c = 0; c < KWIN; c++) {
            const int t = a * KWIN + c;
            float at = __shfl_sync(0xffffffffu, (t < 32) ? e0 : e1, t & 31);
            float2 vv = ((const float2*)(vbase + (size_t)c * QKVN))[lane];
            accx = fmaf(at, vv.x, accx);
            accy = fmaf(at, vv.y, accy);
        }
    }

    __nv_bfloat16 hx = __float2bfloat16(accx);
    __nv_bfloat16 hy = __float2bfloat16(accy);
    __nv_bfloat16 lx = __float2bfloat16(accx - __bfloat162float(hx));
    __nv_bfloat16 ly = __float2bfloat16(accy - __bfloat162float(hy));
    const size_t oidx = (size_t)pix * DIM + h * HD + 2 * lane;
    __nv_bfloat162 ph(hx, hy), pl(lx, ly);
    *(__nv_bfloat162*)(ahi + oidx) = ph;
    *(__nv_bfloat162*)(alo + oidx) = pl;
}

// ---------------------------------------------------------------------------
extern "C" void kernel_launch(void* const* d_in, const int* in_sizes, int n_in,
                              void* d_out, int out_size)
{
    const float* x      = (const float*)d_in[0];
    const float* qkv_w  = (const float*)d_in[1];
    const float* qkv_b  = (const float*)d_in[2];
    const float* rpb    = (const float*)d_in[3];
    const float* proj_w = (const float*)d_in[4];
    const float* proj_b = (const float*)d_in[5];
    float* out = (float*)d_out;

    float *qkv;
    __nv_bfloat16 *xhi, *xlo, *w1hi, *w1lo, *ahi, *alo, *w2hi, *w2lo;
    cudaGetSymbolAddress((void**)&qkv, g_qkv);
    cudaGetSymbolAddress((void**)&xhi, g_xhi);
    cudaGetSymbolAddress((void**)&xlo, g_xlo);
    cudaGetSymbolAddress((void**)&w1hi, g_w1hi);
    cudaGetSymbolAddress((void**)&w1lo, g_w1lo);
    cudaGetSymbolAddress((void**)&ahi, g_ahi);
    cudaGetSymbolAddress((void**)&alo, g_alo);
    cudaGetSymbolAddress((void**)&w2hi, g_w2hi);
    cudaGetSymbolAddress((void**)&w2lo, g_w2lo);

    cudaFuncSetAttribute(gemm_bf16x3,
                         cudaFuncAttributeMaxDynamicSharedMemorySize, GEMM_SMEM);

    // 0) Split all fp32 inputs into bf16 hi/lo (one launch)
    cvt_all<<<(N_X + N_W1 + N_W2) / 1024, 256>>>(
        x, qkv_w, proj_w, xhi, xlo, w1hi, w1lo, w2hi, w2lo);

    // 1) QKV projection
    gemm_bf16x3<<<dim3(QKVN / 64, NPIX / 128), 256, GEMM_SMEM>>>(
        xhi, xlo, w1hi, w1lo, qkv_b, qkv, NPIX, QKVN, DIM);

    // 2) Neighborhood attention (emits bf16 hi/lo directly)
    nat_attn<<<dim3(HWDIM / 8, HWDIM, NHEAD), 256>>>(qkv, rpb, ahi, alo);

    // 3) Output projection
    gemm_bf16x3<<<dim3(DIM / 64, NPIX / 128), 256, GEMM_SMEM>>>(
        ahi, alo, w2hi, w2lo, proj_b, out, NPIX, DIM, DIM);
}

// round 7
// speedup vs baseline: 1.1835x; 1.0629x over previous
#include <cuda_runtime.h>
#include <cuda_bf16.h>
#include <cstdint>
#include <math.h>

// Problem constants
#define HWDIM 80
#define NPIX  6400
#define DIM   512
#define QKVN  1536
#define NHEAD 8
#define HD    64
#define KWIN  7

// Scratch (allocation-free rule: __device__ globals)
__device__ float g_qkv[(size_t)NPIX * QKVN];
__device__ __nv_bfloat16 g_xhi[(size_t)NPIX * DIM];
__device__ __nv_bfloat16 g_xlo[(size_t)NPIX * DIM];
__device__ __nv_bfloat16 g_w1hi[(size_t)QKVN * DIM];
__device__ __nv_bfloat16 g_w1lo[(size_t)QKVN * DIM];
__device__ __nv_bfloat16 g_ahi[(size_t)NPIX * DIM];
__device__ __nv_bfloat16 g_alo[(size_t)NPIX * DIM];
__device__ __nv_bfloat16 g_w2hi[(size_t)DIM * DIM];
__device__ __nv_bfloat16 g_w2lo[(size_t)DIM * DIM];

#define N_X  (NPIX * DIM)
#define N_W1 (QKVN * DIM)
#define N_W2 (DIM * DIM)

// ---------------------------------------------------------------------------
// fp32 -> bf16 hi/lo split for all three inputs in one launch.
// ---------------------------------------------------------------------------
__global__ void __launch_bounds__(256) cvt_all(
    const float* __restrict__ x, const float* __restrict__ w1,
    const float* __restrict__ w2,
    __nv_bfloat16* __restrict__ xhi, __nv_bfloat16* __restrict__ xlo,
    __nv_bfloat16* __restrict__ w1hi, __nv_bfloat16* __restrict__ w1lo,
    __nv_bfloat16* __restrict__ w2hi, __nv_bfloat16* __restrict__ w2lo)
{
    int i = (blockIdx.x * 256 + threadIdx.x) * 4;
    const float* src;
    __nv_bfloat16 *hi, *lo;
    if (i < N_X)              { src = x + i;             hi = xhi + i;  lo = xlo + i; }
    else if (i < N_X + N_W1)  { i -= N_X;  src = w1 + i; hi = w1hi + i; lo = w1lo + i; }
    else                      { i -= N_X + N_W1; src = w2 + i; hi = w2hi + i; lo = w2lo + i; }

    float4 v = *(const float4*)src;
    float f[4] = {v.x, v.y, v.z, v.w};
    __nv_bfloat16 h[4], l[4];
#pragma unroll
    for (int k = 0; k < 4; k++) {
        h[k] = __float2bfloat16(f[k]);
        l[k] = __float2bfloat16(f[k] - __bfloat162float(h[k]));
    }
    uint2 ph, pl;
    {
        __nv_bfloat162 t;
        t = __nv_bfloat162(h[0], h[1]); ph.x = *(uint32_t*)&t;
        t = __nv_bfloat162(h[2], h[3]); ph.y = *(uint32_t*)&t;
        t = __nv_bfloat162(l[0], l[1]); pl.x = *(uint32_t*)&t;
        t = __nv_bfloat162(l[2], l[3]); pl.y = *(uint32_t*)&t;
    }
    *(uint2*)hi = ph;
    *(uint2*)lo = pl;
}

// ---------------------------------------------------------------------------
// mma.sync bf16 GEMM (3xBF16 compensated): C[M,N] = A[M,K] @ B[N,K]^T + bias
// 128x64 CTA tile, 128 threads = 4 warps in 2(m) x 2(n); warp tile 64x32.
// BK=32, 3-stage cp.async, 1 syncthreads/chunk, reg-double-buffered fragments.
// ---------------------------------------------------------------------------
#define BK 32
#define ROWB 80                          // padded row stride (32 bf16 + 16B pad)
#define AMATB (128 * ROWB)               // 10240
#define BMATB (64 * ROWB)                // 5120
#define STAGEB (2 * AMATB + 2 * BMATB)   // 30720
#define GEMM_SMEM (3 * STAGEB)           // 92160

__device__ __forceinline__ uint32_t smem_u32(const void* p) {
    uint32_t a;
    asm("{ .reg .u64 t; cvta.to.shared.u64 t, %1; cvt.u32.u64 %0, t; }"
        : "=r"(a) : "l"(p));
    return a;
}
__device__ __forceinline__ void cp16(uint32_t dst, const void* src) {
    asm volatile("cp.async.cg.shared.global [%0], [%1], 16;"
                 :: "r"(dst), "l"(src));
}
__device__ __forceinline__ void cp_commit() {
    asm volatile("cp.async.commit_group;" ::: "memory");
}
__device__ __forceinline__ void cp_wait1() {
    asm volatile("cp.async.wait_group 1;" ::: "memory");
}
__device__ __forceinline__ void cp_wait0() {
    asm volatile("cp.async.wait_group 0;" ::: "memory");
}
__device__ __forceinline__ void ldmx4(uint32_t* r, uint32_t addr) {
    asm volatile("ldmatrix.sync.aligned.m8n8.x4.shared.b16 {%0,%1,%2,%3}, [%4];"
                 : "=r"(r[0]), "=r"(r[1]), "=r"(r[2]), "=r"(r[3]) : "r"(addr));
}
__device__ __forceinline__ void mma_bf16(float* c, const uint32_t* a, const uint32_t* b) {
    asm volatile(
        "mma.sync.aligned.m16n8k16.row.col.f32.bf16.bf16.f32 "
        "{%0,%1,%2,%3}, {%4,%5,%6,%7}, {%8,%9}, {%0,%1,%2,%3};"
        : "+f"(c[0]), "+f"(c[1]), "+f"(c[2]), "+f"(c[3])
        : "r"(a[0]), "r"(a[1]), "r"(a[2]), "r"(a[3]), "r"(b[0]), "r"(b[1]));
}

__global__ void __launch_bounds__(128, 2) gemm_bf16x3(
    const __nv_bfloat16* __restrict__ Ahi, const __nv_bfloat16* __restrict__ Alo,
    const __nv_bfloat16* __restrict__ Bhi, const __nv_bfloat16* __restrict__ Blo,
    const float* __restrict__ bias, float* __restrict__ C,
    int M, int N, int K)
{
    extern __shared__ char smem[];
    const uint32_t sb = smem_u32(smem);
    const int tid = threadIdx.x;
    const int wid = tid >> 5;
    const int lane = tid & 31;
    const int bm = blockIdx.y * 128;
    const int bn = blockIdx.x * 64;
    const int wm = (wid & 1) * 64;    // warp m offset (64-row tile)
    const int wn = (wid >> 1) * 32;   // warp n offset (32-col tile)

    const __nv_bfloat16* gA[2] = {Ahi + (size_t)bm * K, Alo + (size_t)bm * K};
    const __nv_bfloat16* gB[2] = {Bhi + (size_t)bn * K, Blo + (size_t)bn * K};

    float acc[4][4][4];
#pragma unroll
    for (int mi = 0; mi < 4; mi++)
#pragma unroll
        for (int ni = 0; ni < 4; ni++)
#pragma unroll
            for (int e = 0; e < 4; e++) acc[mi][ni][e] = 0.f;

    const int nch = K / BK;          // 16
    const int row4 = tid >> 2;       // 0..31
    const int chunk = tid & 3;

    // stage = 1536 x 16B over 128 threads = 12 cp16/thread
    auto load_stage = [&](int buf, int k0) {
        const uint32_t st = sb + buf * STAGEB;
#pragma unroll
        for (int m = 0; m < 2; m++) {
#pragma unroll
            for (int rb = 0; rb < 4; rb++) {
                const int r = rb * 32 + row4;
                cp16(st + m * AMATB + r * ROWB + chunk * 16,
                     gA[m] + (size_t)r * K + k0 + chunk * 8);
            }
#pragma unroll
            for (int rb = 0; rb < 2; rb++) {
                const int r = rb * 32 + row4;
                cp16(st + 2 * AMATB + m * BMATB + r * ROWB + chunk * 16,
                     gB[m] + (size_t)r * K + k0 + chunk * 8);
            }
        }
    };

    load_stage(0, 0);      cp_commit();
    load_stage(1, BK);     cp_commit();

    // ldmatrix lane mappings
    const int a_r  = wm + (lane & 15);
    const int a_k  = (lane >> 4) * 8;
    const int b_nr = (lane & 7) + ((lane >> 4) & 1) * 8;
    const int b_k  = ((lane >> 3) & 1) * 8;

    // fragment double buffers
    uint32_t afh[2][4][4], afl[2][4][4], bfh[2][4][2], bfl[2][4][2];

    auto ldsm_frags = [&](uint32_t st, int kk,
                          uint32_t afh_[4][4], uint32_t afl_[4][4],
                          uint32_t bfh_[4][2], uint32_t bfl_[4][2]) {
        const uint32_t bbase = st + 2 * AMATB
            + (uint32_t)((wn + b_nr) * ROWB + (kk * 16 + b_k) * 2);
#pragma unroll
        for (int p = 0; p < 2; p++) {
            uint32_t rh[4], rl[4];
            ldmx4(rh, bbase + p * 16 * ROWB);
            ldmx4(rl, bbase + BMATB + p * 16 * ROWB);
            bfh_[2 * p][0] = rh[0]; bfh_[2 * p][1] = rh[1];
            bfh_[2 * p + 1][0] = rh[2]; bfh_[2 * p + 1][1] = rh[3];
            bfl_[2 * p][0] = rl[0]; bfl_[2 * p][1] = rl[1];
            bfl_[2 * p + 1][0] = rl[2]; bfl_[2 * p + 1][1] = rl[3];
        }
        const uint32_t abase = st
            + (uint32_t)(a_r * ROWB + (kk * 16 + a_k) * 2);
#pragma unroll
        for (int mi = 0; mi < 4; mi++) {
            ldmx4(afh_[mi], abase + mi * 16 * ROWB);
            ldmx4(afl_[mi], abase + AMATB + mi * 16 * ROWB);
        }
    };

    int buf = 0;
    for (int ch = 0; ch < nch; ch++) {
        if (ch + 1 < nch) cp_wait1(); else cp_wait0();
        __syncthreads();
        const int nb = ch + 2;
        if (nb < nch) {
            int b3 = nb - (nb / 3) * 3;
            load_stage(b3, nb * BK);
            cp_commit();
        }

        const uint32_t st = sb + buf * STAGEB;
        ldsm_frags(st, 0, afh[0], afl[0], bfh[0], bfl[0]);
#pragma unroll
        for (int kk = 0; kk < 2; kk++) {
            if (kk == 0)
                ldsm_frags(st, 1, afh[1], afl[1], bfh[1], bfl[1]);
#pragma unroll
            for (int mi = 0; mi < 4; mi++) {
#pragma unroll
                for (int ni = 0; ni < 4; ni++) {
                    mma_bf16(acc[mi][ni], afh[kk][mi], bfh[kk][ni]);
                    mma_bf16(acc[mi][ni], afh[kk][mi], bfl[kk][ni]);
                    mma_bf16(acc[mi][ni], afl[kk][mi], bfh[kk][ni]);
                }
            }
        }
        buf = (buf == 2) ? 0 : buf + 1;
    }

    const int g = lane >> 2;
    const int tg = lane & 3;
#pragma unroll
    for (int mi = 0; mi < 4; mi++) {
        const int r0 = bm + wm + mi * 16 + g;
#pragma unroll
        for (int ni = 0; ni < 4; ni++) {
            const int col = bn + wn + ni * 8 + tg * 2;
            const float2 bv = *(const float2*)(bias + col);
            float2 o0, o1;
            o0.x = acc[mi][ni][0] + bv.x; o0.y = acc[mi][ni][1] + bv.y;
            o1.x = acc[mi][ni][2] + bv.x; o1.y = acc[mi][ni][3] + bv.y;
            *(float2*)(C + (size_t)r0 * N + col) = o0;
            *(float2*)(C + (size_t)(r0 + 8) * N + col) = o1;
        }
    }
}

// ---------------------------------------------------------------------------
// Neighborhood attention: one warp per (pixel, head).
// Score phase: half-warp per neighbor, float4 loads, 4 shfl per 2 neighbors.
// Probs parked in smem; AV reads via LDS broadcast. bf16 hi/lo epilogue.
// ---------------------------------------------------------------------------
__global__ void __launch_bounds__(256) nat_attn(
    const float* __restrict__ qkv, const float* __restrict__ rpb,
    __nv_bfloat16* __restrict__ ahi, __nv_bfloat16* __restrict__ alo)
{
    __shared__ float sprob[8][52];

    const int warp = threadIdx.x >> 5;
    const int lane = threadIdx.x & 31;
    const int j = blockIdx.x * 8 + warp;
    const int i = blockIdx.y;
    const int h = blockIdx.z;
    const int pix = i * HWDIM + j;

    const int sh = min(max(i - 3, 0), HWDIM - KWIN);
    const int sw = min(max(j - 3, 0), HWDIM - KWIN);

    const int half = lane >> 4;    // 0: even neighbor, 1: odd neighbor
    const int l15 = lane & 15;

    // q: lanes of each half hold dims 4*l15 .. 4*l15+3 (scaled)
    float4 q4 = ((const float4*)(qkv + (size_t)pix * QKVN + h * HD))[l15];
    q4.x *= 0.125f; q4.y *= 0.125f; q4.z *= 0.125f; q4.w *= 0.125f;

    const float* rp = rpb + h * 169 + (sh - i + 6) * 13 + (sw - j + 6);
    const float* kb = qkv + (size_t)(sh * HWDIM + sw) * QKVN + DIM + h * HD;

    // --- scores: 2 neighbors per iteration (one per half-warp) ---
#pragma unroll
    for (int it = 0; it < 25; it++) {
        const int t = 2 * it + half;
        const bool valid = (t < 49);
        const int tt = valid ? t : 0;
        const unsigned a = ((unsigned)tt * 37u) >> 8;     // tt / 7
        const int c = tt - 7 * (int)a;
        const float4 kv = ((const float4*)(kb + ((size_t)a * HWDIM + c) * QKVN))[l15];
        float s = q4.x * kv.x + q4.y * kv.y + q4.z * kv.z + q4.w * kv.w;
        s += __shfl_xor_sync(0xffffffffu, s, 1);
        s += __shfl_xor_sync(0xffffffffu, s, 2);
        s += __shfl_xor_sync(0xffffffffu, s, 4);
        s += __shfl_xor_sync(0xffffffffu, s, 8);
        if (l15 == 0 && valid)
            sprob[warp][t] = s + rp[a * 13 + c];
    }
    __syncwarp();

    // --- softmax over 49 scores ---
    float s0 = sprob[warp][lane];
    float s1 = (lane + 32 < 49) ? sprob[warp][lane + 32] : -1e30f;
    if (lane >= 17) s0 = sprob[warp][lane];    // lanes 0..48 all covered; keep
    float m = fmaxf(s0, s1);
#pragma unroll
    for (int o = 16; o; o >>= 1)
        m = fmaxf(m, __shfl_xor_sync(0xffffffffu, m, o));
    float e0 = __expf(s0 - m);
    float e1 = (lane + 32 < 49) ? __expf(s1 - m) : 0.f;
    float sum = e0 + e1;
#pragma unroll
    for (int o = 16; o; o >>= 1)
        sum += __shfl_xor_sync(0xffffffffu, sum, o);
    const float inv = __fdividef(1.f, sum);
    sprob[warp][lane] = e0 * inv;
    if (lane + 32 < 49) sprob[warp][lane + 32] = e1 * inv;
    __syncwarp();

    // --- AV: lane owns dims 2*lane, 2*lane+1 ---
    float ax = 0.f, ay = 0.f;
    const float* vb = qkv + (size_t)(sh * HWDIM + sw) * QKVN + 2 * DIM + h * HD;
#pragma unroll
    for (int a = 0; a < KWIN; a++) {
#pragma unroll
        for (int c = 0; c < KWIN; c++) {
            const float at = sprob[warp][a * 7 + c];
            const float2 vv = ((const float2*)(vb + ((size_t)a * HWDIM + c) * QKVN))[lane];
            ax = fmaf(at, vv.x, ax);
            ay = fmaf(at, vv.y, ay);
        }
    }

    // --- fused bf16 hi/lo epilogue ---
    __nv_bfloat16 hx = __float2bfloat16(ax);
    __nv_bfloat16 hy = __float2bfloat16(ay);
    __nv_bfloat16 lx = __float2bfloat16(ax - __bfloat162float(hx));
    __nv_bfloat16 ly = __float2bfloat16(ay - __bfloat162float(hy));
    const size_t oidx = (size_t)pix * DIM + h * HD + 2 * lane;
    __nv_bfloat162 ph(hx, hy), pl(lx, ly);
    *(__nv_bfloat162*)(ahi + oidx) = ph;
    *(__nv_bfloat162*)(alo + oidx) = pl;
}

// ---------------------------------------------------------------------------
extern "C" void kernel_launch(void* const* d_in, const int* in_sizes, int n_in,
                              void* d_out, int out_size)
{
    const float* x      = (const float*)d_in[0];
    const float* qkv_w  = (const float*)d_in[1];
    const float* qkv_b  = (const float*)d_in[2];
    const float* rpb    = (const float*)d_in[3];
    const float* proj_w = (const float*)d_in[4];
    const float* proj_b = (const float*)d_in[5];
    float* out = (float*)d_out;

    float *qkv;
    __nv_bfloat16 *xhi, *xlo, *w1hi, *w1lo, *ahi, *alo, *w2hi, *w2lo;
    cudaGetSymbolAddress((void**)&qkv, g_qkv);
    cudaGetSymbolAddress((void**)&xhi, g_xhi);
    cudaGetSymbolAddress((void**)&xlo, g_xlo);
    cudaGetSymbolAddress((void**)&w1hi, g_w1hi);
    cudaGetSymbolAddress((void**)&w1lo, g_w1lo);
    cudaGetSymbolAddress((void**)&ahi, g_ahi);
    cudaGetSymbolAddress((void**)&alo, g_alo);
    cudaGetSymbolAddress((void**)&w2hi, g_w2hi);
    cudaGetSymbolAddress((void**)&w2lo, g_w2lo);

    cudaFuncSetAttribute(gemm_bf16x3,
                         cudaFuncAttributeMaxDynamicSharedMemorySize, GEMM_SMEM);

    // 0) Split all fp32 inputs into bf16 hi/lo (one launch)
    cvt_all<<<(N_X + N_W1 + N_W2) / 1024, 256>>>(
        x, qkv_w, proj_w, xhi, xlo, w1hi, w1lo, w2hi, w2lo);

    // 1) QKV projection
    gemm_bf16x3<<<dim3(QKVN / 64, NPIX / 128), 128, GEMM_SMEM>>>(
        xhi, xlo, w1hi, w1lo, qkv_b, qkv, NPIX, QKVN, DIM);

    // 2) Neighborhood attention (emits bf16 hi/lo directly)
    nat_attn<<<dim3(HWDIM / 8, HWDIM, NHEAD), 256>>>(qkv, rpb, ahi, alo);

    // 3) Output projection
    gemm_bf16x3<<<dim3(DIM / 64, NPIX / 128), 128, GEMM_SMEM>>>(
        ahi, alo, w2hi, w2lo, proj_b, out, NPIX, DIM, DIM);
}

// round 8
// speedup vs baseline: 1.2382x; 1.0462x over previous
#include <cuda_runtime.h>
#include <cuda_bf16.h>
#include <cstdint>
#include <math.h>

// Problem constants
#define HWDIM 80
#define NPIX  6400
#define DIM   512
#define QKVN  1536
#define NHEAD 8
#define HD    64
#define KWIN  7

// Scratch (allocation-free rule: __device__ globals)
__device__ float g_qkv[(size_t)NPIX * QKVN];
__device__ __nv_bfloat16 g_xhi[(size_t)NPIX * DIM];
__device__ __nv_bfloat16 g_xlo[(size_t)NPIX * DIM];
__device__ __nv_bfloat16 g_w1hi[(size_t)QKVN * DIM];
__device__ __nv_bfloat16 g_w1lo[(size_t)QKVN * DIM];
__device__ __nv_bfloat16 g_ahi[(size_t)NPIX * DIM];
__device__ __nv_bfloat16 g_alo[(size_t)NPIX * DIM];
__device__ __nv_bfloat16 g_w2hi[(size_t)DIM * DIM];
__device__ __nv_bfloat16 g_w2lo[(size_t)DIM * DIM];

#define N_X  (NPIX * DIM)
#define N_W1 (QKVN * DIM)
#define N_W2 (DIM * DIM)

// ---------------------------------------------------------------------------
// fp32 -> bf16 hi/lo split for all three inputs in one launch.
// ---------------------------------------------------------------------------
__global__ void __launch_bounds__(256) cvt_all(
    const float* __restrict__ x, const float* __restrict__ w1,
    const float* __restrict__ w2,
    __nv_bfloat16* __restrict__ xhi, __nv_bfloat16* __restrict__ xlo,
    __nv_bfloat16* __restrict__ w1hi, __nv_bfloat16* __restrict__ w1lo,
    __nv_bfloat16* __restrict__ w2hi, __nv_bfloat16* __restrict__ w2lo)
{
    int i = (blockIdx.x * 256 + threadIdx.x) * 4;
    const float* src;
    __nv_bfloat16 *hi, *lo;
    if (i < N_X)              { src = x + i;             hi = xhi + i;  lo = xlo + i; }
    else if (i < N_X + N_W1)  { i -= N_X;  src = w1 + i; hi = w1hi + i; lo = w1lo + i; }
    else                      { i -= N_X + N_W1; src = w2 + i; hi = w2hi + i; lo = w2lo + i; }

    float4 v = *(const float4*)src;
    float f[4] = {v.x, v.y, v.z, v.w};
    __nv_bfloat16 h[4], l[4];
#pragma unroll
    for (int k = 0; k < 4; k++) {
        h[k] = __float2bfloat16(f[k]);
        l[k] = __float2bfloat16(f[k] - __bfloat162float(h[k]));
    }
    uint2 ph, pl;
    {
        __nv_bfloat162 t;
        t = __nv_bfloat162(h[0], h[1]); ph.x = *(uint32_t*)&t;
        t = __nv_bfloat162(h[2], h[3]); ph.y = *(uint32_t*)&t;
        t = __nv_bfloat162(l[0], l[1]); pl.x = *(uint32_t*)&t;
        t = __nv_bfloat162(l[2], l[3]); pl.y = *(uint32_t*)&t;
    }
    *(uint2*)hi = ph;
    *(uint2*)lo = pl;
}

// ---------------------------------------------------------------------------
// mma.sync bf16 GEMM (3xBF16 compensated): C[M,N] = A[M,K] @ B[N,K]^T + bias
// 128 x BN CTA tile (BN = 96 or 128), 256 threads = 8 warps in 2(m) x 4(n);
// warp tile 64 x (BN/4). BK=32, 2-stage cp.async, ONE syncthreads per chunk.
// ---------------------------------------------------------------------------
#define BK 32
#define ROWB 80                          // padded row stride (32 bf16 + 16B pad)
#define AMATB (128 * ROWB)               // 10240

__device__ __forceinline__ uint32_t smem_u32(const void* p) {
    uint32_t a;
    asm("{ .reg .u64 t; cvta.to.shared.u64 t, %1; cvt.u32.u64 %0, t; }"
        : "=r"(a) : "l"(p));
    return a;
}
__device__ __forceinline__ void cp16(uint32_t dst, const void* src) {
    asm volatile("cp.async.cg.shared.global [%0], [%1], 16;"
                 :: "r"(dst), "l"(src));
}
__device__ __forceinline__ void cp_commit() {
    asm volatile("cp.async.commit_group;" ::: "memory");
}
__device__ __forceinline__ void cp_wait0() {
    asm volatile("cp.async.wait_group 0;" ::: "memory");
}
__device__ __forceinline__ void ldmx4(uint32_t* r, uint32_t addr) {
    asm volatile("ldmatrix.sync.aligned.m8n8.x4.shared.b16 {%0,%1,%2,%3}, [%4];"
                 : "=r"(r[0]), "=r"(r[1]), "=r"(r[2]), "=r"(r[3]) : "r"(addr));
}
__device__ __forceinline__ void ldmx2(uint32_t* r, uint32_t addr) {
    asm volatile("ldmatrix.sync.aligned.m8n8.x2.shared.b16 {%0,%1}, [%2];"
                 : "=r"(r[0]), "=r"(r[1]) : "r"(addr));
}
__device__ __forceinline__ void mma_bf16(float* c, const uint32_t* a, const uint32_t* b) {
    asm volatile(
        "mma.sync.aligned.m16n8k16.row.col.f32.bf16.bf16.f32 "
        "{%0,%1,%2,%3}, {%4,%5,%6,%7}, {%8,%9}, {%0,%1,%2,%3};"
        : "+f"(c[0]), "+f"(c[1]), "+f"(c[2]), "+f"(c[3])
        : "r"(a[0]), "r"(a[1]), "r"(a[2]), "r"(a[3]), "r"(b[0]), "r"(b[1]));
}

template<int BN>
__global__ void __launch_bounds__(256, 2) gemm_bf16x3(
    const __nv_bfloat16* __restrict__ Ahi, const __nv_bfloat16* __restrict__ Alo,
    const __nv_bfloat16* __restrict__ Bhi, const __nv_bfloat16* __restrict__ Blo,
    const float* __restrict__ bias, float* __restrict__ C,
    int M, int N, int K)
{
    constexpr int NI = BN / 32;                 // n-steps of 8 per warp (3 or 4)
    constexpr int BMB = BN * ROWB;              // B matrix tile bytes
    constexpr int STAGE = 2 * AMATB + 2 * BMB;
    constexpr int NT4 = (256 + 2 * BN) / 64;    // cp16 per thread per stage

    extern __shared__ char smem[];
    const uint32_t sb = smem_u32(smem);
    const int tid = threadIdx.x;
    const int wid = tid >> 5;
    const int lane = tid & 31;
    const int bm = blockIdx.y * 128;
    const int bn = blockIdx.x * BN;
    const int wm = (wid & 1) * 64;              // warp m offset
    const int wn = (wid >> 1) * (BN / 4);       // warp n offset

    const __nv_bfloat16* gAhi = Ahi + (size_t)bm * K;
    const __nv_bfloat16* gAlo = Alo + (size_t)bm * K;
    const __nv_bfloat16* gBhi = Bhi + (size_t)bn * K;
    const __nv_bfloat16* gBlo = Blo + (size_t)bn * K;

    float acc[4][NI][4];
#pragma unroll
    for (int mi = 0; mi < 4; mi++)
#pragma unroll
        for (int ni = 0; ni < NI; ni++)
#pragma unroll
            for (int e = 0; e < 4; e++) acc[mi][ni][e] = 0.f;

    const int nch = K / BK;

    auto load_stage = [&](int buf, int k0) {
        const uint32_t st = sb + buf * STAGE;
#pragma unroll
        for (int it = 0; it < NT4; it++) {
            const int f = tid + it * 256;
            const int r = f >> 2;
            const int c = f & 3;
            const __nv_bfloat16* src;
            uint32_t dst;
            if (r < 128)          { src = gAhi + (size_t)r * K;
                                    dst = st + r * ROWB; }
            else if (r < 256)     { src = gAlo + (size_t)(r - 128) * K;
                                    dst = st + AMATB + (r - 128) * ROWB; }
            else if (r < 256 + BN){ src = gBhi + (size_t)(r - 256) * K;
                                    dst = st + 2 * AMATB + (r - 256) * ROWB; }
            else                  { src = gBlo + (size_t)(r - 256 - BN) * K;
                                    dst = st + 2 * AMATB + BMB + (r - 256 - BN) * ROWB; }
            cp16(dst + c * 16, src + k0 + c * 8);
        }
    };

    // ldmatrix lane mappings
    const int a_r  = wm + (lane & 15);
    const int a_k  = (lane >> 4) * 8;
    const int b_nr = (lane & 7) + ((lane >> 4) & 1) * 8;   // for paired x4
    const int b_k  = ((lane >> 3) & 1) * 8;

    load_stage(0, 0);
    cp_commit();

    for (int ch = 0; ch < nch; ch++) {
        cp_wait0();
        __syncthreads();
        if (ch + 1 < nch) {
            load_stage((ch + 1) & 1, (ch + 1) * BK);
            cp_commit();
        }

        const uint32_t st = sb + (ch & 1) * STAGE;
#pragma unroll
        for (int kk = 0; kk < 2; kk++) {
            uint32_t bh[NI][2], bl[NI][2];
            const uint32_t bb = st + 2 * AMATB + (uint32_t)((kk * 16 + b_k) * 2);
#pragma unroll
            for (int p = 0; p < NI / 2; p++) {
                uint32_t rh[4], rl[4];
                const uint32_t addr = bb + (wn + p * 16 + b_nr) * ROWB;
                ldmx4(rh, addr);
                ldmx4(rl, addr + BMB);
                bh[2 * p][0] = rh[0]; bh[2 * p][1] = rh[1];
                bh[2 * p + 1][0] = rh[2]; bh[2 * p + 1][1] = rh[3];
                bl[2 * p][0] = rl[0]; bl[2 * p][1] = rl[1];
                bl[2 * p + 1][0] = rl[2]; bl[2 * p + 1][1] = rl[3];
            }
            if (NI & 1) {
                // remainder single n-step via ldmx2 (R3 mapping)
                const uint32_t addr = st + 2 * AMATB
                    + (uint32_t)((wn + (NI - 1) * 8 + (lane & 7)) * ROWB
                                 + (kk * 16 + b_k) * 2);
                ldmx2(bh[NI - 1], addr);
                ldmx2(bl[NI - 1], addr + BMB);
            }
            const uint32_t ab = st + (uint32_t)(a_r * ROWB + (kk * 16 + a_k) * 2);
#pragma unroll
            for (int mi = 0; mi < 4; mi++) {
                uint32_t ah[4], al[4];
                ldmx4(ah, ab + mi * 16 * ROWB);
                ldmx4(al, ab + AMATB + mi * 16 * ROWB);
#pragma unroll
                for (int ni = 0; ni < NI; ni++) {
                    mma_bf16(acc[mi][ni], ah, bh[ni]);
                    mma_bf16(acc[mi][ni], ah, bl[ni]);
                    mma_bf16(acc[mi][ni], al, bh[ni]);
                }
            }
        }
    }

    const int g = lane >> 2;
    const int tg = lane & 3;
#pragma unroll
    for (int mi = 0; mi < 4; mi++) {
        const int r0 = bm + wm + mi * 16 + g;
#pragma unroll
        for (int ni = 0; ni < NI; ni++) {
            const int col = bn + wn + ni * 8 + tg * 2;
            const float2 bv = *(const float2*)(bias + col);
            float2 o0, o1;
            o0.x = acc[mi][ni][0] + bv.x; o0.y = acc[mi][ni][1] + bv.y;
            o1.x = acc[mi][ni][2] + bv.x; o1.y = acc[mi][ni][3] + bv.y;
            *(float2*)(C + (size_t)r0 * N + col) = o0;
            *(float2*)(C + (size_t)(r0 + 8) * N + col) = o1;
        }
    }
}

#define GEMM_SMEM_96  (2 * (2 * AMATB + 2 * 96 * ROWB))    // 71680
#define GEMM_SMEM_128 (2 * (2 * AMATB + 2 * 128 * ROWB))   // 81920

// ---------------------------------------------------------------------------
// Neighborhood attention: one warp per (pixel, head).
// Score phase: half-warp per neighbor, float4 loads, 4 shfl per 2 neighbors.
// Probs parked in smem; AV reads via LDS broadcast. bf16 hi/lo epilogue.
// ---------------------------------------------------------------------------
__global__ void __launch_bounds__(256) nat_attn(
    const float* __restrict__ qkv, const float* __restrict__ rpb,
    __nv_bfloat16* __restrict__ ahi, __nv_bfloat16* __restrict__ alo)
{
    __shared__ float sprob[8][52];

    const int warp = threadIdx.x >> 5;
    const int lane = threadIdx.x & 31;
    const int j = blockIdx.x * 8 + warp;
    const int i = blockIdx.y;
    const int h = blockIdx.z;
    const int pix = i * HWDIM + j;

    const int sh = min(max(i - 3, 0), HWDIM - KWIN);
    const int sw = min(max(j - 3, 0), HWDIM - KWIN);

    const int half = lane >> 4;
    const int l15 = lane & 15;

    float4 q4 = ((const float4*)(qkv + (size_t)pix * QKVN + h * HD))[l15];
    q4.x *= 0.125f; q4.y *= 0.125f; q4.z *= 0.125f; q4.w *= 0.125f;

    const float* rp = rpb + h * 169 + (sh - i + 6) * 13 + (sw - j + 6);
    const float* kb = qkv + (size_t)(sh * HWDIM + sw) * QKVN + DIM + h * HD;

#pragma unroll
    for (int it = 0; it < 25; it++) {
        const int t = 2 * it + half;
        const bool valid = (t < 49);
        const int tt = valid ? t : 0;
        const unsigned a = ((unsigned)tt * 37u) >> 8;
        const int c = tt - 7 * (int)a;
        const float4 kv = ((const float4*)(kb + ((size_t)a * HWDIM + c) * QKVN))[l15];
        float s = q4.x * kv.x + q4.y * kv.y + q4.z * kv.z + q4.w * kv.w;
        s += __shfl_xor_sync(0xffffffffu, s, 1);
        s += __shfl_xor_sync(0xffffffffu, s, 2);
        s += __shfl_xor_sync(0xffffffffu, s, 4);
        s += __shfl_xor_sync(0xffffffffu, s, 8);
        if (l15 == 0 && valid)
            sprob[warp][t] = s + rp[a * 13 + c];
    }
    __syncwarp();

    float s0 = sprob[warp][lane];
    float s1 = (lane + 32 < 49) ? sprob[warp][lane + 32] : -1e30f;
    float m = fmaxf(s0, s1);
#pragma unroll
    for (int o = 16; o; o >>= 1)
        m = fmaxf(m, __shfl_xor_sync(0xffffffffu, m, o));
    float e0 = __expf(s0 - m);
    float e1 = (lane + 32 < 49) ? __expf(s1 - m) : 0.f;
    float sum = e0 + e1;
#pragma unroll
    for (int o = 16; o; o >>= 1)
        sum += __shfl_xor_sync(0xffffffffu, sum, o);
    const float inv = __fdividef(1.f, sum);
    sprob[warp][lane] = e0 * inv;
    if (lane + 32 < 49) sprob[warp][lane + 32] = e1 * inv;
    __syncwarp();

    float ax = 0.f, ay = 0.f;
    const float* vb = qkv + (size_t)(sh * HWDIM + sw) * QKVN + 2 * DIM + h * HD;
#pragma unroll
    for (int a = 0; a < KWIN; a++) {
#pragma unroll
        for (int c = 0; c < KWIN; c++) {
            const float at = sprob[warp][a * 7 + c];
            const float2 vv = ((const float2*)(vb + ((size_t)a * HWDIM + c) * QKVN))[lane];
            ax = fmaf(at, vv.x, ax);
            ay = fmaf(at, vv.y, ay);
        }
    }

    __nv_bfloat16 hx = __float2bfloat16(ax);
    __nv_bfloat16 hy = __float2bfloat16(ay);
    __nv_bfloat16 lx = __float2bfloat16(ax - __bfloat162float(hx));
    __nv_bfloat16 ly = __float2bfloat16(ay - __bfloat162float(hy));
    const size_t oidx = (size_t)pix * DIM + h * HD + 2 * lane;
    __nv_bfloat162 ph(hx, hy), pl(lx, ly);
    *(__nv_bfloat162*)(ahi + oidx) = ph;
    *(__nv_bfloat162*)(alo + oidx) = pl;
}

// ---------------------------------------------------------------------------
extern "C" void kernel_launch(void* const* d_in, const int* in_sizes, int n_in,
                              void* d_out, int out_size)
{
    const float* x      = (const float*)d_in[0];
    const float* qkv_w  = (const float*)d_in[1];
    const float* qkv_b  = (const float*)d_in[2];
    const float* rpb    = (const float*)d_in[3];
    const float* proj_w = (const float*)d_in[4];
    const float* proj_b = (const float*)d_in[5];
    float* out = (float*)d_out;

    float *qkv;
    __nv_bfloat16 *xhi, *xlo, *w1hi, *w1lo, *ahi, *alo, *w2hi, *w2lo;
    cudaGetSymbolAddress((void**)&qkv, g_qkv);
    cudaGetSymbolAddress((void**)&xhi, g_xhi);
    cudaGetSymbolAddress((void**)&xlo, g_xlo);
    cudaGetSymbolAddress((void**)&w1hi, g_w1hi);
    cudaGetSymbolAddress((void**)&w1lo, g_w1lo);
    cudaGetSymbolAddress((void**)&ahi, g_ahi);
    cudaGetSymbolAddress((void**)&alo, g_alo);
    cudaGetSymbolAddress((void**)&w2hi, g_w2hi);
    cudaGetSymbolAddress((void**)&w2lo, g_w2lo);

    cudaFuncSetAttribute(gemm_bf16x3<96>,
                         cudaFuncAttributeMaxDynamicSharedMemorySize, GEMM_SMEM_96);
    cudaFuncSetAttribute(gemm_bf16x3<128>,
                         cudaFuncAttributeMaxDynamicSharedMemorySize, GEMM_SMEM_128);

    // 0) Split all fp32 inputs into bf16 hi/lo (one launch)
    cvt_all<<<(N_X + N_W1 + N_W2) / 1024, 256>>>(
        x, qkv_w, proj_w, xhi, xlo, w1hi, w1lo, w2hi, w2lo);

    // 1) QKV projection: 128x96 tiles (800 CTAs)
    gemm_bf16x3<96><<<dim3(QKVN / 96, NPIX / 128), 256, GEMM_SMEM_96>>>(
        xhi, xlo, w1hi, w1lo, qkv_b, qkv, NPIX, QKVN, DIM);

    // 2) Neighborhood attention (emits bf16 hi/lo directly)
    nat_attn<<<dim3(HWDIM / 8, HWDIM, NHEAD), 256>>>(qkv, rpb, ahi, alo);

    // 3) Output projection: 128x128 tiles (200 CTAs, single wave)
    gemm_bf16x3<128><<<dim3(DIM / 128, NPIX / 128), 256, GEMM_SMEM_128>>>(
        ahi, alo, w2hi, w2lo, proj_b, out, NPIX, DIM, DIM);
}